// round 3
// baseline (speedup 1.0000x reference)
#include <cuda_runtime.h>

#define TPB    256
#define PAIRS  8          // row-pairs per thread (16 rows)

// Weight layout in constant memory:
// [0:24)  W1 (3x8 row-major)   [24:32) b1
// [32:64) W2 (8x4 row-major)   [64:68) b2
// [68:72) W3                   [72] b3   [73] w
__device__    float g_stage[80];
__constant__  float cw[80];

__global__ void gather_weights(
    const float* __restrict__ W1, const float* __restrict__ b1,
    const float* __restrict__ W2, const float* __restrict__ b2,
    const float* __restrict__ W3, const float* __restrict__ b3,
    const float* __restrict__ w)
{
    const int i = threadIdx.x;
    if (i < 24)       g_stage[i] = W1[i];
    else if (i < 32)  g_stage[i] = b1[i - 24];
    else if (i < 64)  g_stage[i] = W2[i - 32];
    else if (i < 68)  g_stage[i] = b2[i - 64];
    else if (i < 72)  g_stage[i] = W3[i - 68];
    else if (i == 72) g_stage[i] = b3[0];
    else if (i == 73) g_stage[i] = w[0];
}

__device__ __forceinline__ float tanha(float x) {
    float y;
    asm("tanh.approx.f32 %0, %1;" : "=f"(y) : "f"(x));
    return y;
}

__device__ __forceinline__ float eval_row(float x0, float x1) {
    // quantum feature
    const float q = __sinf(x0) * __sinf(x1 + cw[73]);

    float h1[8];
#pragma unroll
    for (int j = 0; j < 8; ++j) {
        float a = fmaf(cw[0 * 8 + j], x0, cw[24 + j]);
        a = fmaf(cw[1 * 8 + j], x1, a);
        a = fmaf(cw[2 * 8 + j], q, a);
        h1[j] = tanha(a);
    }

    float h2[4];
#pragma unroll
    for (int j = 0; j < 4; ++j) {
        float a = cw[64 + j];
#pragma unroll
        for (int i = 0; i < 8; ++i) a = fmaf(h1[i], cw[32 + i * 4 + j], a);
        h2[j] = tanha(a);
    }

    float o = cw[72];
#pragma unroll
    for (int j = 0; j < 4; ++j) o = fmaf(h2[j], cw[68 + j], o);
    return o;
}

__global__ void __launch_bounds__(TPB, 4) qnn_kernel(
    const float4* __restrict__ in,   // 2 rows per float4
    float2*       __restrict__ out,  // 2 outputs per float2
    int npairs, int pstride, int nrows,
    const float* __restrict__ in_scalar, float* __restrict__ out_scalar)
{
    const int t = blockIdx.x * TPB + threadIdx.x;

    if (t < pstride) {
        const bool full = (t + (PAIRS - 1) * pstride) < npairs;
        if (full) {
#pragma unroll 2
            for (int k = 0; k < PAIRS; ++k) {
                const int p = t + k * pstride;          // coalesced float4
                const float4 v = __ldg(in + p);
                float2 o;
                o.x = eval_row(v.x, v.y);
                o.y = eval_row(v.z, v.w);
                out[p] = o;
            }
        } else {
            for (int k = 0; k < PAIRS; ++k) {
                const int p = t + k * pstride;
                if (p >= npairs) break;
                const float4 v = __ldg(in + p);
                float2 o;
                o.x = eval_row(v.x, v.y);
                o.y = eval_row(v.z, v.w);
                out[p] = o;
            }
        }
    }

    // odd trailing row (nrows not divisible by 2): one thread handles it
    if ((nrows & 1) && t == 0) {
        const float x0 = __ldg(in_scalar + (nrows - 1) * 2);
        const float x1 = __ldg(in_scalar + (nrows - 1) * 2 + 1);
        out_scalar[nrows - 1] = eval_row(x0, x1);
    }
}

extern "C" void kernel_launch(void* const* d_in, const int* in_sizes, int n_in,
                              void* d_out, int out_size)
{
    const float* in = (const float*)d_in[0];
    const int nrows  = in_sizes[0] / 2;
    const int npairs = nrows / 2;

    // Stage the tiny model into __constant__ (graph-capturable: kernel + async D2D memcpy)
    gather_weights<<<1, 128>>>(
        (const float*)d_in[1], (const float*)d_in[2],
        (const float*)d_in[3], (const float*)d_in[4],
        (const float*)d_in[5], (const float*)d_in[6],
        (const float*)d_in[7]);
    void* stage_addr = nullptr;
    cudaGetSymbolAddress(&stage_addr, g_stage);
    cudaMemcpyToSymbolAsync(cw, stage_addr, 80 * sizeof(float), 0,
                            cudaMemcpyDeviceToDevice, 0);

    const int pstride = (npairs + PAIRS - 1) / PAIRS;   // threads needed
    const int blocks  = (pstride + TPB - 1) / TPB;

    qnn_kernel<<<blocks > 0 ? blocks : 1, TPB>>>(
        (const float4*)in, (float2*)d_out,
        npairs, pstride, nrows,
        in, (float*)d_out);
}

// round 6
// speedup vs baseline: 1.0014x; 1.0014x over previous
#include <cuda_runtime.h>

#define TPB     256
#define NBLOCKS 592        // 148 SMs x 4 CTAs/SM: exactly one resident wave

// Weight layout in constant memory:
// [0:24)  W1 (3x8 row-major)   [24:32) b1
// [32:64) W2 (8x4 row-major)   [64:68) b2
// [68:72) W3                   [72] b3   [73] w
__device__    float g_stage[80];
__constant__  float cw[80];

__global__ void gather_weights(
    const float* __restrict__ W1, const float* __restrict__ b1,
    const float* __restrict__ W2, const float* __restrict__ b2,
    const float* __restrict__ W3, const float* __restrict__ b3,
    const float* __restrict__ w)
{
    const int i = threadIdx.x;
    if (i < 24)       g_stage[i] = W1[i];
    else if (i < 32)  g_stage[i] = b1[i - 24];
    else if (i < 64)  g_stage[i] = W2[i - 32];
    else if (i < 68)  g_stage[i] = b2[i - 64];
    else if (i < 72)  g_stage[i] = W3[i - 68];
    else if (i == 72) g_stage[i] = b3[0];
    else if (i == 73) g_stage[i] = w[0];
}

__device__ __forceinline__ float tanha(float x) {
    float y;
    asm("tanh.approx.f32 %0, %1;" : "=f"(y) : "f"(x));
    return y;
}

__device__ __forceinline__ float eval_row(float x0, float x1) {
    // quantum feature: sin(x0) * sin(x1 + w)
    const float q = __sinf(x0) * __sinf(x1 + cw[73]);

    float h1[8];
#pragma unroll
    for (int j = 0; j < 8; ++j) {
        float a = fmaf(cw[0 * 8 + j], x0, cw[24 + j]);
        a = fmaf(cw[1 * 8 + j], x1, a);
        a = fmaf(cw[2 * 8 + j], q, a);
        h1[j] = tanha(a);
    }

    float h2[4];
#pragma unroll
    for (int j = 0; j < 4; ++j) {
        float a = cw[64 + j];
#pragma unroll
        for (int i = 0; i < 8; ++i) a = fmaf(h1[i], cw[32 + i * 4 + j], a);
        h2[j] = tanha(a);
    }

    float o = cw[72];
#pragma unroll
    for (int j = 0; j < 4; ++j) o = fmaf(h2[j], cw[68 + j], o);
    return o;
}

__global__ void __launch_bounds__(TPB, 4) qnn_kernel(
    const float4* __restrict__ in,   // 2 rows per float4
    float2*       __restrict__ out,  // 2 outputs per float2
    int npairs, int nrows,
    const float* __restrict__ in_scalar, float* __restrict__ out_scalar)
{
    const int t      = blockIdx.x * TPB + threadIdx.x;
    const int stride = NBLOCKS * TPB;

    // Strided loop over row-pairs: one resident wave, balanced to +/-1 iter.
#pragma unroll 2
    for (int p = t; p < npairs; p += stride) {
        const float4 v = __ldg(in + p);
        float2 o;
        o.x = eval_row(v.x, v.y);
        o.y = eval_row(v.z, v.w);
        out[p] = o;
    }

    // odd trailing row (nrows not divisible by 2): one thread handles it
    if ((nrows & 1) && t == 0) {
        const float x0 = __ldg(in_scalar + (nrows - 1) * 2);
        const float x1 = __ldg(in_scalar + (nrows - 1) * 2 + 1);
        out_scalar[nrows - 1] = eval_row(x0, x1);
    }
}

extern "C" void kernel_launch(void* const* d_in, const int* in_sizes, int n_in,
                              void* d_out, int out_size)
{
    const float* in = (const float*)d_in[0];
    const int nrows  = in_sizes[0] / 2;
    const int npairs = nrows / 2;

    // Stage the tiny model into __constant__ (graph-capturable: kernel + async D2D memcpy)
    gather_weights<<<1, 128>>>(
        (const float*)d_in[1], (const float*)d_in[2],
        (const float*)d_in[3], (const float*)d_in[4],
        (const float*)d_in[5], (const float*)d_in[6],
        (const float*)d_in[7]);
    void* stage_addr = nullptr;
    cudaGetSymbolAddress(&stage_addr, g_stage);
    cudaMemcpyToSymbolAsync(cw, stage_addr, 80 * sizeof(float), 0,
                            cudaMemcpyDeviceToDevice, 0);

    qnn_kernel<<<NBLOCKS, TPB>>>(
        (const float4*)in, (float2*)d_out,
        npairs, nrows,
        in, (float*)d_out);
}